// round 6
// baseline (speedup 1.0000x reference)
#include <cuda_runtime.h>
#include <cuda_bf16.h>
#include <mma.h>
#include <math.h>
#include <float.h>
#include <stdint.h>

using namespace nvcuda;

#define BN   64
#define LN   512
#define HN   512
#define EMBN 512
#define VN   50257
#define TSTEPS 32
#define H3   1536
#define KSPLIT 4

#define VROWS 128
#define NTILES ((VN + VROWS - 1) / VROWS)   // 393
#define VPAD   (NTILES * VROWS)             // 50304 (padded vocab rows)

// ---------------- scratch (static device globals; no allocation) ----------------
__device__ __align__(16) float g_gictx[BN*H3];
__device__ __align__(16) float g_h1[BN*HN];
__device__ __align__(16) float g_h2[BN*HN];
__device__ int   g_seq[BN];
__device__ __align__(16) float g_gi[KSPLIT*BN*H3];
__device__ __align__(16) float g_gh[KSPLIT*BN*H3];
__device__ float g_pval[NTILES*BN];
__device__ int   g_pidx[NTILES*BN];
// split-bf16 weights / activations for tensor-core logits (padded rows zeroed)
__device__ __align__(16) __nv_bfloat16 g_whi[(size_t)VPAD*HN];
__device__ __align__(16) __nv_bfloat16 g_wlo[(size_t)VPAD*HN];
__device__ __align__(16) __nv_bfloat16 g_h2hi[BN*HN];
__device__ __align__(16) __nv_bfloat16 g_h2lo[BN*HN];

// packed fp32x2 FMA (Blackwell)
__device__ __forceinline__ void fma2(unsigned long long &c,
                                     unsigned long long a,
                                     unsigned long long b) {
    asm("fma.rn.f32x2 %0, %1, %2, %3;" : "=l"(c) : "l"(a), "l"(b), "l"(c));
}

// ---------------- one-time setup ----------------
__global__ void __launch_bounds__(256) k_setup(
    const float* __restrict__ enc, const int* __restrict__ elen,
    const int* __restrict__ sos,
    const float* __restrict__ Wk,
    const float* __restrict__ Wih1, const float* __restrict__ bih1)
{
    __shared__ float s_mean[HN];
    __shared__ float s_ctx[HN];
    int b = blockIdx.x, t = threadIdx.x;
    int len = elen[b];
    float inv = 1.f / (float)len;

    for (int h = t; h < HN; h += 256) {
        const float* p = enc + (size_t)b * LN * HN + h;
        float s = 0.f;
        for (int l = 0; l < len; ++l) s += p[(size_t)l * HN];
        s_mean[h] = s * inv;
    }
    g_h1[b*HN + t] = 0.f; g_h1[b*HN + t + 256] = 0.f;
    g_h2[b*HN + t] = 0.f; g_h2[b*HN + t + 256] = 0.f;
    if (t == 0) g_seq[b] = sos[0];
    __syncthreads();

    const float4* m4 = (const float4*)s_mean;
    for (int p = t; p < HN; p += 256) {
        const float4* w = (const float4*)(Wk + (size_t)p * HN);
        float acc = 0.f;
        for (int h = 0; h < HN/4; ++h) {
            float4 a = m4[h], ww = w[h];
            acc += a.x*ww.x + a.y*ww.y + a.z*ww.z + a.w*ww.w;
        }
        s_ctx[p] = acc;
    }
    __syncthreads();

    const float4* c4 = (const float4*)s_ctx;
    for (int j = t; j < H3; j += 256) {
        const float4* w = (const float4*)(Wih1 + (size_t)j * (EMBN + HN) + EMBN);
        float acc = bih1[j];
        for (int h = 0; h < HN/4; ++h) {
            float4 a = c4[h], ww = w[h];
            acc += a.x*ww.x + a.y*ww.y + a.z*ww.z + a.w*ww.w;
        }
        g_gictx[b*H3 + j] = acc;
    }
}

// split Wout -> bf16 hi/lo; zero the padded rows (one-time)
__global__ void k_wsplit(const float* __restrict__ W) {
    size_t i = (size_t)blockIdx.x * 256 + threadIdx.x;
    if (i < (size_t)VPAD * HN) {
        if (i < (size_t)VN * HN) {
            float w = W[i];
            __nv_bfloat16 hi = __float2bfloat16(w);
            g_whi[i] = hi;
            g_wlo[i] = __float2bfloat16(w - __bfloat162float(hi));
        } else {
            g_whi[i] = __float2bfloat16(0.f);
            g_wlo[i] = __float2bfloat16(0.f);
        }
    }
}

// ---------------- per-step GRU pre-activation GEMMs (K-split 4) ----------------
__global__ void __launch_bounds__(256) k_gru_gemm(
    int layer,
    const float* __restrict__ emb,
    const float* __restrict__ Wi, int wsi,
    const float* __restrict__ Wh)
{
    __shared__ __align__(16) float As2[32][132];
    __shared__ __align__(16) float Bs[32][68];

    const int j0 = blockIdx.x * 64;
    const int kz = blockIdx.y;
    const int zi = blockIdx.z;

    const float* W; int ws; const float* A; int gather;
    if (zi == 0) { W = Wi; ws = wsi; gather = (layer == 1); A = (layer == 1) ? emb : g_h1; }
    else         { W = Wh; ws = HN;  gather = 0;            A = (layer == 1) ? g_h1 : g_h2; }
    float* Out = (zi == 0 ? g_gi : g_gh) + kz * (BN * H3);

    const int tid = threadIdx.x;
    const int tx = tid & 15, ty = tid >> 4;

    unsigned long long acc[4][2];
#pragma unroll
    for (int i = 0; i < 4; i++) { acc[i][0] = 0ULL; acc[i][1] = 0ULL; }

    int ab[2], ak[2]; const float* arow[2];
    int bn[2], bk[2];
#pragma unroll
    for (int r = 0; r < 2; r++) {
        int idx = tid + 256*r;
        ab[r] = idx >> 3; ak[r] = (idx & 7) << 2;
        arow[r] = gather ? (emb + (size_t)g_seq[ab[r]] * EMBN) : (A + ab[r]*HN);
        bn[r] = idx >> 3; bk[r] = (idx & 7) << 2;
    }

    const int k0 = kz * 128;
    float4 pa[2], pb[2];
#pragma unroll
    for (int r = 0; r < 2; r++) pa[r] = *(const float4*)(arow[r] + k0 + ak[r]);
#pragma unroll
    for (int r = 0; r < 2; r++) pb[r] = *(const float4*)(W + (size_t)(j0+bn[r])*ws + k0 + bk[r]);

    for (int kt = 0; kt < 4; ++kt) {
        __syncthreads();
#pragma unroll
        for (int r = 0; r < 2; r++) {
            float v[4] = {pa[r].x, pa[r].y, pa[r].z, pa[r].w};
#pragma unroll
            for (int jj = 0; jj < 4; jj++) {
                As2[ak[r]+jj][2*ab[r]]   = v[jj];
                As2[ak[r]+jj][2*ab[r]+1] = v[jj];
            }
        }
#pragma unroll
        for (int r = 0; r < 2; r++) {
            float v[4] = {pb[r].x, pb[r].y, pb[r].z, pb[r].w};
#pragma unroll
            for (int jj = 0; jj < 4; jj++) Bs[bk[r]+jj][bn[r]] = v[jj];
        }
        __syncthreads();
        if (kt + 1 < 4) {
            int k1 = k0 + (kt+1)*32;
#pragma unroll
            for (int r = 0; r < 2; r++) pa[r] = *(const float4*)(arow[r] + k1 + ak[r]);
#pragma unroll
            for (int r = 0; r < 2; r++) pb[r] = *(const float4*)(W + (size_t)(j0+bn[r])*ws + k1 + bk[r]);
        }
#pragma unroll
        for (int kk = 0; kk < 32; ++kk) {
            ulonglong2 a01 = *(const ulonglong2*)&As2[kk][ty*8];
            ulonglong2 a23 = *(const ulonglong2*)&As2[kk][ty*8+4];
            ulonglong2 b01 = *(const ulonglong2*)&Bs[kk][tx*4];
            unsigned long long av[4] = {a01.x, a01.y, a23.x, a23.y};
#pragma unroll
            for (int i = 0; i < 4; i++) {
                fma2(acc[i][0], av[i], b01.x);
                fma2(acc[i][1], av[i], b01.y);
            }
        }
    }

#pragma unroll
    for (int i = 0; i < 4; i++) {
        int b = ty*4 + i;
#pragma unroll
        for (int jp = 0; jp < 2; jp++) {
            float lo = __uint_as_float((unsigned)(acc[i][jp] & 0xffffffffULL));
            float hi = __uint_as_float((unsigned)(acc[i][jp] >> 32));
            int j = j0 + tx*4 + 2*jp;
            Out[b*H3 + j]   = lo;
            Out[b*H3 + j+1] = hi;
        }
    }
}

// ---------------- GRU gates; layer 2 also emits bf16 hi/lo split of h2 ----------------
__global__ void k_gates(int layer,
                        const float* __restrict__ bih2,
                        const float* __restrict__ bhh)
{
    int idx = blockIdx.x * 256 + threadIdx.x;
    int b = idx >> 9, k = idx & 511;

    float bir, biz, bin;
    if (layer == 1) {
        const float* base = g_gictx + b*H3;
        bir = base[k]; biz = base[k+512]; bin = base[k+1024];
    } else {
        bir = bih2[k]; biz = bih2[k+512]; bin = bih2[k+1024];
    }
    float ir = bir, iz = biz, in_ = bin;
    float hr = bhh[k], hz = bhh[k+512], hn = bhh[k+1024];
#pragma unroll
    for (int s = 0; s < KSPLIT; s++) {
        const float* gi = g_gi + s*(BN*H3) + b*H3;
        const float* gh = g_gh + s*(BN*H3) + b*H3;
        ir  += gi[k];      iz += gi[k+512];  in_ += gi[k+1024];
        hr  += gh[k];      hz += gh[k+512];  hn  += gh[k+1024];
    }

    float* h = (layer == 1) ? g_h1 : g_h2;
    float hv = h[idx];
    float r = 1.f / (1.f + expf(-(ir + hr)));
    float z = 1.f / (1.f + expf(-(iz + hz)));
    float n = tanhf(in_ + r * hn);
    float hnew = (1.f - z) * n + z * hv;
    h[idx] = hnew;
    if (layer == 2) {
        __nv_bfloat16 hi = __float2bfloat16(hnew);
        g_h2hi[idx] = hi;
        g_h2lo[idx] = __float2bfloat16(hnew - __bfloat162float(hi));
    }
}

// ---------------- WMMA logits: D[128v x 64b] = W @ h2^T via split-bf16 x3 ----------------
// 8 warps; warp w owns vocab rows [v0 + 16w, +16). Frags loaded straight from
// L2-resident globals. Epilogue via padded smem tile (stride 68) with fused argmax.
#define SVST 68   // smem row stride (multiple of 4, != 0 mod 32 -> low conflict)

__global__ void __launch_bounds__(256) k_logits_wmma(
    const float* __restrict__ bout,
    float* __restrict__ out)
{
    __shared__ float sv[8][16*SVST];
    const int tid = threadIdx.x;
    const int wid = tid >> 5;
    const int v0 = blockIdx.x * VROWS;
    const int vw = v0 + wid*16;   // padded arrays: always in-bounds

    wmma::fragment<wmma::accumulator, 16,16,16, float> c[4];
#pragma unroll
    for (int n = 0; n < 4; ++n) wmma::fill_fragment(c[n], 0.f);

    for (int k = 0; k < HN; k += 16) {
        wmma::fragment<wmma::matrix_a, 16,16,16, __nv_bfloat16, wmma::row_major> ahi, alo;
        wmma::load_matrix_sync(ahi, g_whi + (size_t)vw*HN + k, HN);
        wmma::load_matrix_sync(alo, g_wlo + (size_t)vw*HN + k, HN);
#pragma unroll
        for (int n = 0; n < 4; ++n) {
            wmma::fragment<wmma::matrix_b, 16,16,16, __nv_bfloat16, wmma::col_major> bhi, blo;
            wmma::load_matrix_sync(bhi, g_h2hi + (size_t)(n*16)*HN + k, HN);
            wmma::load_matrix_sync(blo, g_h2lo + (size_t)(n*16)*HN + k, HN);
            wmma::mma_sync(c[n], ahi, bhi, c[n]);
            wmma::mma_sync(c[n], ahi, blo, c[n]);
            wmma::mma_sync(c[n], alo, bhi, c[n]);
        }
    }
#pragma unroll
    for (int n = 0; n < 4; ++n)
        wmma::store_matrix_sync(&sv[wid][n*16], c[n], SVST, wmma::mem_row_major);
    __syncthreads();

    // fused argmax: 4 threads per b, each scans 32 v rows
    {
        int b = tid >> 2, part = tid & 3;
        float mv = -FLT_MAX; int mi = 0x7fffffff;
#pragma unroll 4
        for (int i = 0; i < 32; ++i) {
            int v = part*32 + i;
            int gv = v0 + v;
            if (gv < VN) {
                float x = sv[v>>4][(v&15)*SVST + b] + bout[gv];
                if (x > mv) { mv = x; mi = gv; }
            }
        }
#pragma unroll
        for (int o = 1; o < 4; o <<= 1) {
            float om = __shfl_xor_sync(0xffffffffu, mv, o);
            int   oi = __shfl_xor_sync(0xffffffffu, mi, o);
            if (om > mv || (om == mv && oi < mi)) { mv = om; mi = oi; }
        }
        if (part == 0) {
            g_pval[(size_t)blockIdx.x*BN + b] = mv;
            g_pidx[(size_t)blockIdx.x*BN + b] = mi;
        }
    }

    // coalesced write-out with bias
    {
        int v = tid & 127;
        int gv = v0 + v;
        int bb = tid >> 7;   // 0 or 1
        if (gv < VN) {
            float bias = bout[gv];
            const float* row = &sv[v>>4][(v&15)*SVST];
#pragma unroll
            for (int it = 0; it < 32; ++it) {
                int b = it*2 + bb;
                out[(size_t)b*VN + gv] = row[b] + bias;
            }
        }
    }
}

// ---------------- final argmax reduce over tiles ----------------
__global__ void k_amax_final() {
    int b = blockIdx.x, t = threadIdx.x;
    float mval = -FLT_MAX; int midx = 0x7fffffff;
    for (int s = t; s < NTILES; s += 256) {
        float v = g_pval[(size_t)s*BN + b]; int ix = g_pidx[(size_t)s*BN + b];
        if (v > mval || (v == mval && ix < midx)) { mval = v; midx = ix; }
    }
    __shared__ float sv[256];
    __shared__ int   si[256];
    sv[t] = mval; si[t] = midx;
    __syncthreads();
    for (int s = 128; s > 0; s >>= 1) {
        if (t < s) {
            if (sv[t+s] > sv[t] || (sv[t+s] == sv[t] && si[t+s] < si[t])) {
                sv[t] = sv[t+s]; si[t] = si[t+s];
            }
        }
        __syncthreads();
    }
    if (t == 0) g_seq[b] = si[0];
}

// ---------------- launch ----------------
extern "C" void kernel_launch(void* const* d_in, const int* in_sizes, int n_in,
                              void* d_out, int out_size) {
    const float* encoded = (const float*)d_in[0];
    const int*   elen    = (const int*)  d_in[1];
    const int*   sos     = (const int*)  d_in[2];
    const float* emb     = (const float*)d_in[4];
    const float* Wk      = (const float*)d_in[5];
    const float* Wih1    = (const float*)d_in[6];
    const float* Whh1    = (const float*)d_in[7];
    const float* bih1    = (const float*)d_in[8];
    const float* bhh1    = (const float*)d_in[9];
    const float* Wih2    = (const float*)d_in[10];
    const float* Whh2    = (const float*)d_in[11];
    const float* bih2    = (const float*)d_in[12];
    const float* bhh2    = (const float*)d_in[13];
    const float* Wout    = (const float*)d_in[14];
    const float* bout    = (const float*)d_in[15];
    float* out = (float*)d_out;

    k_setup<<<BN, 256>>>(encoded, elen, sos, Wk, Wih1, bih1);
    k_wsplit<<<(int)(((size_t)VPAD*HN + 255)/256), 256>>>(Wout);

    for (int t = 0; t < TSTEPS; ++t) {
        k_gru_gemm<<<dim3(24, KSPLIT, 2), 256>>>(1, emb, Wih1, EMBN + HN, Whh1);
        k_gates<<<(BN*HN)/256, 256>>>(1, nullptr, bhh1);
        k_gru_gemm<<<dim3(24, KSPLIT, 2), 256>>>(2, emb, Wih2, HN, Whh2);
        k_gates<<<(BN*HN)/256, 256>>>(2, bih2, bhh2);
        float* out_t = out + (size_t)t * BN * VN;
        k_logits_wmma<<<NTILES, 256>>>(bout, out_t);
        if (t + 1 < TSTEPS) k_amax_final<<<BN, 256>>>();
    }
}